// round 1
// baseline (speedup 1.0000x reference)
#include <cuda_runtime.h>

#define SNUM 65536
#define MDIM 256
#define ENUM 8
#define HDIM 1024
#define CAP  20480          // TOP_K * int(1.25 * S/E) = 2 * 10240
#define NB   8192           // gating blocks, 8 tokens each

// ---------------- scratch (device globals; no allocations allowed) ----------
__device__ int   g_topi[SNUM * 2];
__device__ float g_topv[SNUM * 2];
__device__ int   g_blockcnt[NB * 16];     // per-block counts, [block][e*2+k]
__device__ int   g_blockoff[NB * 16];     // exclusive prefix per (e,k) series
__device__ float g_blockgate[NB * ENUM];  // per-block gate sums (for l_loss)
__device__ int   g_k1base[ENUM];          // total k0 count per expert
__device__ int   g_cnt[ENUM];             // rows actually used per expert
__device__ int   g_src[ENUM * CAP];       // slot -> source token
__device__ int   g_tokslot[SNUM * 2];     // token,k -> slot (or -1)
__device__ float g_h [(size_t)ENUM * CAP * HDIM];  // hidden activations (671 MB)
__device__ float g_eo[(size_t)ENUM * CAP * MDIM];  // expert outputs (167 MB)

// ---------------- 1) gating: logits, softmax, top-2, per-block counts -------
__global__ __launch_bounds__(256) void k_gate(const float* __restrict__ x,
                                              const float* __restrict__ wg) {
    __shared__ float wgs[ENUM * MDIM];   // 8 KB
    __shared__ int   scnt[16];
    __shared__ float sg[8][ENUM];        // per-warp gate vectors (deterministic reduce)
    int tid = threadIdx.x;
    for (int i = tid; i < ENUM * MDIM; i += 256) wgs[i] = wg[i];
    if (tid < 16) scnt[tid] = 0;
    __syncthreads();

    int warp = tid >> 5, lane = tid & 31;
    int s = blockIdx.x * 8 + warp;
    const float* xr = x + (size_t)s * MDIM;

    float part[ENUM];
#pragma unroll
    for (int e = 0; e < ENUM; e++) part[e] = 0.f;
#pragma unroll
    for (int i = 0; i < 8; i++) {
        float v = xr[i * 32 + lane];
#pragma unroll
        for (int e = 0; e < ENUM; e++) part[e] += v * wgs[e * MDIM + i * 32 + lane];
    }
#pragma unroll
    for (int e = 0; e < ENUM; e++) {
#pragma unroll
        for (int off = 16; off; off >>= 1)
            part[e] += __shfl_xor_sync(0xffffffffu, part[e], off);
    }

    if (lane == 0) {
        float mx = part[0];
#pragma unroll
        for (int e = 1; e < ENUM; e++) mx = fmaxf(mx, part[e]);
        float p[ENUM]; float sum = 0.f;
#pragma unroll
        for (int e = 0; e < ENUM; e++) { p[e] = expf(part[e] - mx); sum += p[e]; }
        float inv = 1.f / sum;
#pragma unroll
        for (int e = 0; e < ENUM; e++) { p[e] *= inv; sg[warp][e] = p[e]; }
        // top-2 (strict > keeps lowest index on ties, matching lax.top_k)
        int i0 = 0; float v0 = p[0];
#pragma unroll
        for (int e = 1; e < ENUM; e++) if (p[e] > v0) { v0 = p[e]; i0 = e; }
        int i1 = -1; float v1 = -1.f;
#pragma unroll
        for (int e = 0; e < ENUM; e++) if (e != i0 && p[e] > v1) { v1 = p[e]; i1 = e; }
        g_topi[s * 2 + 0] = i0;  g_topi[s * 2 + 1] = i1;
        g_topv[s * 2 + 0] = v0;  g_topv[s * 2 + 1] = v1;
        atomicAdd(&scnt[i0 * 2 + 0], 1);
        atomicAdd(&scnt[i1 * 2 + 1], 1);
    }
    __syncthreads();
    if (tid < 16) g_blockcnt[blockIdx.x * 16 + tid] = scnt[tid];
    if (tid < ENUM) {   // deterministic (fixed-order) block gate sum
        float a = 0.f;
#pragma unroll
        for (int w = 0; w < 8; w++) a += sg[w][tid];
        g_blockgate[blockIdx.x * ENUM + tid] = a;
    }
}

// ---------------- 2) single-block scan over block counts + l_loss ----------
__global__ __launch_bounds__(512) void k_scan(float* lossPtr) {
    int tid = threadIdx.x, w = tid >> 5, lane = tid & 31;
    __shared__ int   s_tot[16];
    __shared__ float s_gs[ENUM];
    // 16 warps: warp w scans series w (e = w/2, k = w&1) over NB blocks
    int carry = 0;
    for (int c = 0; c < NB / 32; c++) {
        int idx = c * 32 + lane;
        int v = g_blockcnt[idx * 16 + w];
        int inc = v;
#pragma unroll
        for (int off = 1; off < 32; off <<= 1) {
            int t = __shfl_up_sync(0xffffffffu, inc, off);
            if (lane >= off) inc += t;
        }
        g_blockoff[idx * 16 + w] = carry + inc - v;   // exclusive
        carry += __shfl_sync(0xffffffffu, inc, 31);
    }
    if (lane == 0) s_tot[w] = carry;
    if (w < ENUM) {  // deterministic gate-sum reduction for expert w
        float acc = 0.f;
        for (int c = 0; c < NB / 32; c++)
            acc += g_blockgate[(c * 32 + lane) * ENUM + w];
#pragma unroll
        for (int off = 16; off; off >>= 1)
            acc += __shfl_xor_sync(0xffffffffu, acc, off);
        if (lane == 0) s_gs[w] = acc;
    }
    __syncthreads();
    if (tid == 0) {
        float loss = 0.f;
        for (int e = 0; e < ENUM; e++) {
            float me = s_gs[e] / (float)SNUM;
            float ce = (float)s_tot[e * 2] / (float)SNUM;
            loss += me * ce;
        }
        loss *= (float)ENUM;
        if (lossPtr) *lossPtr = loss;
        for (int e = 0; e < ENUM; e++) {
            g_k1base[e] = s_tot[e * 2];
            int t = s_tot[e * 2] + s_tot[e * 2 + 1];
            g_cnt[e] = t < CAP ? t : CAP;
        }
    }
}

// ---------------- 3) routing: within-block rank -> slot assignment ---------
__global__ __launch_bounds__(256) void k_route() {
    __shared__ int ch[8][2];
    int tid = threadIdx.x, warp = tid >> 5, lane = tid & 31;
    int s = blockIdx.x * 8 + warp;
    if (lane < 2) ch[warp][lane] = g_topi[s * 2 + lane];
    __syncthreads();
    if (tid < 16) {
        int t = tid >> 1, k = tid & 1;
        int s2 = blockIdx.x * 8 + t;
        int e = ch[t][k];
        int rank = 0;
#pragma unroll
        for (int u = 0; u < 8; u++) rank += (u < t) && (ch[u][k] == e);
        int pos = g_blockoff[blockIdx.x * 16 + e * 2 + k] + rank
                + (k ? g_k1base[e] : 0);
        int slot = -1;
        if (pos < CAP) { slot = e * CAP + pos; g_src[slot] = s2; }
        g_tokslot[s2 * 2 + k] = slot;
    }
}

// ---------------- 4) GEMM1: h = relu(gather(x) @ w1 + b1), 64x64x16 tiles --
__global__ __launch_bounds__(256) void k_ffn1(const float* __restrict__ x,
                                              const float* __restrict__ w1,
                                              const float* __restrict__ b1) {
    int e = blockIdx.z;
    int cnt = g_cnt[e];
    int row0 = blockIdx.x * 64;
    if (row0 >= cnt) return;
    int j0 = blockIdx.y * 64;

    __shared__ float As[16][64];
    __shared__ float Bs[16][64];
    __shared__ int   ssrc[64];
    int tid = threadIdx.x;
    if (tid < 64) {
        int r = row0 + tid;
        ssrc[tid] = (r < cnt) ? g_src[e * CAP + r] : 0;
    }
    __syncthreads();

    int ty = tid >> 4, tx = tid & 15;
    int ar = tid >> 2, akq = (tid & 3) << 2;
    const float* w1e = w1 + (size_t)e * MDIM * HDIM;
    const float* xA  = x + (size_t)ssrc[ar] * MDIM + akq;

    float acc[4][4];
#pragma unroll
    for (int i = 0; i < 4; i++)
#pragma unroll
        for (int j = 0; j < 4; j++) acc[i][j] = 0.f;

    for (int k0 = 0; k0 < MDIM; k0 += 16) {
        float4 av = *(const float4*)(xA + k0);
        float4 bv = *(const float4*)(w1e + (size_t)(k0 + ty) * HDIM + j0 + (tx << 2));
        __syncthreads();
        As[akq + 0][ar] = av.x; As[akq + 1][ar] = av.y;
        As[akq + 2][ar] = av.z; As[akq + 3][ar] = av.w;
        *(float4*)&Bs[ty][tx << 2] = bv;
        __syncthreads();
#pragma unroll
        for (int kk = 0; kk < 16; kk++) {
            float4 a = *(const float4*)&As[kk][ty << 2];
            float4 b = *(const float4*)&Bs[kk][tx << 2];
            acc[0][0] += a.x*b.x; acc[0][1] += a.x*b.y; acc[0][2] += a.x*b.z; acc[0][3] += a.x*b.w;
            acc[1][0] += a.y*b.x; acc[1][1] += a.y*b.y; acc[1][2] += a.y*b.z; acc[1][3] += a.y*b.w;
            acc[2][0] += a.z*b.x; acc[2][1] += a.z*b.y; acc[2][2] += a.z*b.z; acc[2][3] += a.z*b.w;
            acc[3][0] += a.w*b.x; acc[3][1] += a.w*b.y; acc[3][2] += a.w*b.z; acc[3][3] += a.w*b.w;
        }
    }
    float4 bb = *(const float4*)(b1 + e * HDIM + j0 + (tx << 2));
#pragma unroll
    for (int i = 0; i < 4; i++) {
        int r = row0 + (ty << 2) + i;
        if (r < cnt) {
            float4 o;
            o.x = fmaxf(acc[i][0] + bb.x, 0.f);
            o.y = fmaxf(acc[i][1] + bb.y, 0.f);
            o.z = fmaxf(acc[i][2] + bb.z, 0.f);
            o.w = fmaxf(acc[i][3] + bb.w, 0.f);
            *(float4*)&g_h[((size_t)e * CAP + r) * HDIM + j0 + (tx << 2)] = o;
        }
    }
}

// ---------------- 5) GEMM2: eo = h @ w2 + b2 --------------------------------
__global__ __launch_bounds__(256) void k_ffn2(const float* __restrict__ w2,
                                              const float* __restrict__ b2) {
    int e = blockIdx.z;
    int cnt = g_cnt[e];
    int row0 = blockIdx.x * 64;
    if (row0 >= cnt) return;
    int j0 = blockIdx.y * 64;

    __shared__ float As[16][64];
    __shared__ float Bs[16][64];
    int tid = threadIdx.x;
    int ty = tid >> 4, tx = tid & 15;
    int ar = tid >> 2, akq = (tid & 3) << 2;
    int arow = row0 + ar; if (arow >= cnt) arow = cnt - 1;   // safe duplicate read
    const float* w2e = w2 + (size_t)e * HDIM * MDIM;
    const float* hA  = g_h + ((size_t)e * CAP + arow) * HDIM + akq;

    float acc[4][4];
#pragma unroll
    for (int i = 0; i < 4; i++)
#pragma unroll
        for (int j = 0; j < 4; j++) acc[i][j] = 0.f;

    for (int k0 = 0; k0 < HDIM; k0 += 16) {
        float4 av = *(const float4*)(hA + k0);
        float4 bv = *(const float4*)(w2e + (size_t)(k0 + ty) * MDIM + j0 + (tx << 2));
        __syncthreads();
        As[akq + 0][ar] = av.x; As[akq + 1][ar] = av.y;
        As[akq + 2][ar] = av.z; As[akq + 3][ar] = av.w;
        *(float4*)&Bs[ty][tx << 2] = bv;
        __syncthreads();
#pragma unroll
        for (int kk = 0; kk < 16; kk++) {
            float4 a = *(const float4*)&As[kk][ty << 2];
            float4 b = *(const float4*)&Bs[kk][tx << 2];
            acc[0][0] += a.x*b.x; acc[0][1] += a.x*b.y; acc[0][2] += a.x*b.z; acc[0][3] += a.x*b.w;
            acc[1][0] += a.y*b.x; acc[1][1] += a.y*b.y; acc[1][2] += a.y*b.z; acc[1][3] += a.y*b.w;
            acc[2][0] += a.z*b.x; acc[2][1] += a.z*b.y; acc[2][2] += a.z*b.z; acc[2][3] += a.z*b.w;
            acc[3][0] += a.w*b.x; acc[3][1] += a.w*b.y; acc[3][2] += a.w*b.z; acc[3][3] += a.w*b.w;
        }
    }
    float4 bb = *(const float4*)(b2 + e * MDIM + j0 + (tx << 2));
#pragma unroll
    for (int i = 0; i < 4; i++) {
        int r = row0 + (ty << 2) + i;
        if (r < cnt) {
            float4 o;
            o.x = acc[i][0] + bb.x;
            o.y = acc[i][1] + bb.y;
            o.z = acc[i][2] + bb.z;
            o.w = acc[i][3] + bb.w;
            *(float4*)&g_eo[((size_t)e * CAP + r) * MDIM + j0 + (tx << 2)] = o;
        }
    }
}

// ---------------- 6) combine: y[s] = v0*eo[slot0] + v1*eo[slot1] ------------
__global__ __launch_bounds__(256) void k_combine(float* __restrict__ y) {
    int tid = threadIdx.x;
    int s = blockIdx.x * 4 + (tid >> 6);
    int m = (tid & 63) << 2;
    int sl0 = g_tokslot[s * 2 + 0], sl1 = g_tokslot[s * 2 + 1];
    float v0 = g_topv[s * 2 + 0],  v1 = g_topv[s * 2 + 1];
    float rx = 0.f, ry = 0.f, rz = 0.f, rw = 0.f;
    if (sl0 >= 0) {
        float4 a = *(const float4*)&g_eo[(size_t)sl0 * MDIM + m];
        rx += v0 * a.x; ry += v0 * a.y; rz += v0 * a.z; rw += v0 * a.w;
    }
    if (sl1 >= 0) {
        float4 a = *(const float4*)&g_eo[(size_t)sl1 * MDIM + m];
        rx += v1 * a.x; ry += v1 * a.y; rz += v1 * a.z; rw += v1 * a.w;
    }
    float4 o = {rx, ry, rz, rw};
    *(float4*)&y[(size_t)s * MDIM + m] = o;
}

// ---------------- launch -----------------------------------------------------
extern "C" void kernel_launch(void* const* d_in, const int* in_sizes, int n_in,
                              void* d_out, int out_size) {
    const float* x  = (const float*)d_in[0];
    const float* wg = (const float*)d_in[1];
    const float* w1 = (const float*)d_in[2];
    const float* b1 = (const float*)d_in[3];
    const float* w2 = (const float*)d_in[4];
    const float* b2 = (const float*)d_in[5];
    float* y = (float*)d_out;
    float* lossPtr = (out_size > SNUM * MDIM) ? (y + (size_t)SNUM * MDIM) : nullptr;

    k_gate   <<<NB, 256>>>(x, wg);
    k_scan   <<<1, 512>>>(lossPtr);
    k_route  <<<NB, 256>>>();
    k_ffn1   <<<dim3(CAP / 64, HDIM / 64, ENUM), 256>>>(x, w1, b1);
    k_ffn2   <<<dim3(CAP / 64, MDIM / 64, ENUM), 256>>>(w2, b2);
    k_combine<<<SNUM / 4, 256>>>(y);
}

// round 4
// speedup vs baseline: 3.4652x; 3.4652x over previous
#include <cuda_runtime.h>
#include <cstdint>

#define SNUM 65536
#define MDIM 256
#define ENUM 8
#define HDIM 1024
#define CAP  20480          // TOP_K * int(1.25 * S/E)
#define NB   8192           // gating blocks, 8 tokens each

// ---------------- scratch (device globals; no allocations allowed) ----------
__device__ int   g_topi[SNUM * 2];
__device__ float g_topv[SNUM * 2];
__device__ int   g_blockcnt[NB * 16];
__device__ int   g_blockoff[NB * 16];
__device__ float g_blockgate[NB * ENUM];
__device__ int   g_k1base[ENUM];
__device__ int   g_cnt[ENUM];
__device__ int   g_src[ENUM * CAP];
__device__ int   g_tokslot[SNUM * 2];
__device__ float g_xr [(size_t)SNUM * MDIM];          // tf32-rounded x
__device__ float g_w1t[(size_t)ENUM * HDIM * MDIM];   // [E][1024][256] tf32-rounded
__device__ float g_w2t[(size_t)ENUM * MDIM * HDIM];   // [E][256][1024] tf32-rounded
__device__ float g_h [(size_t)ENUM * CAP * HDIM];     // hidden (tf32-rounded fp32)
__device__ float g_eo[(size_t)ENUM * CAP * MDIM];     // expert outputs fp32

// ---------------- helpers ----------------------------------------------------
__device__ __forceinline__ uint32_t smem_to_u32(const void* p) {
    uint32_t a;
    asm("{ .reg .u64 t; cvta.to.shared.u64 t, %1; cvt.u32.u64 %0, t; }" : "=r"(a) : "l"(p));
    return a;
}
__device__ __forceinline__ float rna_tf32(float f) {
    uint32_t u; asm("cvt.rna.tf32.f32 %0, %1;" : "=r"(u) : "f"(f));
    return __uint_as_float(u);
}
__device__ __forceinline__ void cp16(uint32_t dst, const void* src) {
    asm volatile("cp.async.cg.shared.global [%0], [%1], 16;" :: "r"(dst), "l"(src) : "memory");
}
#define CP_COMMIT() asm volatile("cp.async.commit_group;" ::: "memory")

__device__ __forceinline__ void ldsm4(uint32_t* r, uint32_t addr) {
    asm volatile("ldmatrix.sync.aligned.m8n8.x4.shared.b16 {%0,%1,%2,%3}, [%4];"
                 : "=r"(r[0]), "=r"(r[1]), "=r"(r[2]), "=r"(r[3]) : "r"(addr));
}
__device__ __forceinline__ void ldsm2(uint32_t* r, uint32_t addr) {
    asm volatile("ldmatrix.sync.aligned.m8n8.x2.shared.b16 {%0,%1}, [%2];"
                 : "=r"(r[0]), "=r"(r[1]) : "r"(addr));
}
__device__ __forceinline__ void mma_tf32(float* c, const uint32_t* a, const uint32_t* b) {
    asm volatile("mma.sync.aligned.m16n8k8.row.col.f32.tf32.tf32.f32 "
                 "{%0,%1,%2,%3}, {%4,%5,%6,%7}, {%8,%9}, {%0,%1,%2,%3};"
                 : "+f"(c[0]), "+f"(c[1]), "+f"(c[2]), "+f"(c[3])
                 : "r"(a[0]), "r"(a[1]), "r"(a[2]), "r"(a[3]), "r"(b[0]), "r"(b[1]));
}

// ---------------- 0a) round x to tf32 ----------------------------------------
__global__ __launch_bounds__(256) void k_xround(const float* __restrict__ x,
                                                float* __restrict__ xr) {
    size_t i = ((size_t)blockIdx.x * 256 + threadIdx.x) * 4;
    float4 v = *(const float4*)(x + i);
    v.x = rna_tf32(v.x); v.y = rna_tf32(v.y);
    v.z = rna_tf32(v.z); v.w = rna_tf32(v.w);
    *(float4*)(xr + i) = v;
}

// ---------------- 0b) transpose + tf32-round weights -------------------------
// out[e][c][r] = rna(in[e][r][c]);  grid (C/32, R/32, E), block (32,8)
__global__ void k_transpose(const float* __restrict__ in, float* __restrict__ out,
                            int R, int C) {
    __shared__ float t[32][33];
    int e = blockIdx.z;
    const float* ine = in + (size_t)e * R * C;
    float* oute = out + (size_t)e * R * C;
    int c0 = blockIdx.x * 32, r0 = blockIdx.y * 32;
    int tx = threadIdx.x, ty = threadIdx.y;
#pragma unroll
    for (int i = 0; i < 4; i++)
        t[ty + i * 8][tx] = rna_tf32(ine[(size_t)(r0 + ty + i * 8) * C + c0 + tx]);
    __syncthreads();
#pragma unroll
    for (int i = 0; i < 4; i++)
        oute[(size_t)(c0 + ty + i * 8) * R + r0 + tx] = t[tx][ty + i * 8];
}

// ---------------- 1) gating --------------------------------------------------
__global__ __launch_bounds__(256) void k_gate(const float* __restrict__ x,
                                              const float* __restrict__ wg) {
    __shared__ float wgs[ENUM * MDIM];
    __shared__ int   scnt[16];
    __shared__ float sg[8][ENUM];
    int tid = threadIdx.x;
    for (int i = tid; i < ENUM * MDIM; i += 256) wgs[i] = wg[i];
    if (tid < 16) scnt[tid] = 0;
    __syncthreads();

    int warp = tid >> 5, lane = tid & 31;
    int s = blockIdx.x * 8 + warp;
    const float* xr = x + (size_t)s * MDIM;

    float part[ENUM];
#pragma unroll
    for (int e = 0; e < ENUM; e++) part[e] = 0.f;
#pragma unroll
    for (int i = 0; i < 8; i++) {
        float v = xr[i * 32 + lane];
#pragma unroll
        for (int e = 0; e < ENUM; e++) part[e] += v * wgs[e * MDIM + i * 32 + lane];
    }
#pragma unroll
    for (int e = 0; e < ENUM; e++) {
#pragma unroll
        for (int off = 16; off; off >>= 1)
            part[e] += __shfl_xor_sync(0xffffffffu, part[e], off);
    }

    if (lane == 0) {
        float mx = part[0];
#pragma unroll
        for (int e = 1; e < ENUM; e++) mx = fmaxf(mx, part[e]);
        float p[ENUM]; float sum = 0.f;
#pragma unroll
        for (int e = 0; e < ENUM; e++) { p[e] = expf(part[e] - mx); sum += p[e]; }
        float inv = 1.f / sum;
#pragma unroll
        for (int e = 0; e < ENUM; e++) { p[e] *= inv; sg[warp][e] = p[e]; }
        int i0 = 0; float v0 = p[0];
#pragma unroll
        for (int e = 1; e < ENUM; e++) if (p[e] > v0) { v0 = p[e]; i0 = e; }
        int i1 = -1; float v1 = -1.f;
#pragma unroll
        for (int e = 0; e < ENUM; e++) if (e != i0 && p[e] > v1) { v1 = p[e]; i1 = e; }
        g_topi[s * 2 + 0] = i0;  g_topi[s * 2 + 1] = i1;
        g_topv[s * 2 + 0] = v0;  g_topv[s * 2 + 1] = v1;
        atomicAdd(&scnt[i0 * 2 + 0], 1);
        atomicAdd(&scnt[i1 * 2 + 1], 1);
    }
    __syncthreads();
    if (tid < 16) g_blockcnt[blockIdx.x * 16 + tid] = scnt[tid];
    if (tid < ENUM) {
        float a = 0.f;
#pragma unroll
        for (int w = 0; w < 8; w++) a += sg[w][tid];
        g_blockgate[blockIdx.x * ENUM + tid] = a;
    }
}

// ---------------- 2) scan + loss ---------------------------------------------
__global__ __launch_bounds__(512) void k_scan(float* lossPtr) {
    int tid = threadIdx.x, w = tid >> 5, lane = tid & 31;
    __shared__ int   s_tot[16];
    __shared__ float s_gs[ENUM];
    int carry = 0;
    for (int c = 0; c < NB / 32; c++) {
        int idx = c * 32 + lane;
        int v = g_blockcnt[idx * 16 + w];
        int inc = v;
#pragma unroll
        for (int off = 1; off < 32; off <<= 1) {
            int t = __shfl_up_sync(0xffffffffu, inc, off);
            if (lane >= off) inc += t;
        }
        g_blockoff[idx * 16 + w] = carry + inc - v;
        carry += __shfl_sync(0xffffffffu, inc, 31);
    }
    if (lane == 0) s_tot[w] = carry;
    if (w < ENUM) {
        float acc = 0.f;
        for (int c = 0; c < NB / 32; c++)
            acc += g_blockgate[(c * 32 + lane) * ENUM + w];
#pragma unroll
        for (int off = 16; off; off >>= 1)
            acc += __shfl_xor_sync(0xffffffffu, acc, off);
        if (lane == 0) s_gs[w] = acc;
    }
    __syncthreads();
    if (tid == 0) {
        float loss = 0.f;
        for (int e = 0; e < ENUM; e++) {
            float me = s_gs[e] / (float)SNUM;
            float ce = (float)s_tot[e * 2] / (float)SNUM;
            loss += me * ce;
        }
        loss *= (float)ENUM;
        if (lossPtr) *lossPtr = loss;
        for (int e = 0; e < ENUM; e++) {
            g_k1base[e] = s_tot[e * 2];
            int t = s_tot[e * 2] + s_tot[e * 2 + 1];
            g_cnt[e] = t < CAP ? t : CAP;
        }
    }
}

// ---------------- 3) routing -------------------------------------------------
__global__ __launch_bounds__(256) void k_route() {
    __shared__ int ch[8][2];
    int tid = threadIdx.x, warp = tid >> 5, lane = tid & 31;
    int s = blockIdx.x * 8 + warp;
    if (lane < 2) ch[warp][lane] = g_topi[s * 2 + lane];
    __syncthreads();
    if (tid < 16) {
        int t = tid >> 1, k = tid & 1;
        int s2 = blockIdx.x * 8 + t;
        int e = ch[t][k];
        int rank = 0;
#pragma unroll
        for (int u = 0; u < 8; u++) rank += (u < t) && (ch[u][k] == e);
        int pos = g_blockoff[blockIdx.x * 16 + e * 2 + k] + rank
                + (k ? g_k1base[e] : 0);
        int slot = -1;
        if (pos < CAP) { slot = e * CAP + pos; g_src[slot] = s2; }
        g_tokslot[s2 * 2 + k] = slot;
    }
}

// ---------------- 4/5) tf32 mma.sync GEMM, tile 128x128x32, 4-stage ---------
// smem per stage: A 128x32 fp32 (16KB, 128B-XOR swizzled) + B 128x32 (16KB)
#define STAGES 4
#define SMEM_BYTES (STAGES * 32768)

template<int NK, int NTOT, bool GATHER, bool RELU>
__global__ __launch_bounds__(256, 1) void k_mma(
    const float* __restrict__ Ag, const float* __restrict__ Bg,
    const float* __restrict__ biasG, float* __restrict__ Cg)
{
    constexpr int KDIM = NK * 32;
    int e = blockIdx.z;
    int cnt = g_cnt[e];
    int row0 = blockIdx.x * 128;
    if (row0 >= cnt) return;
    int j0 = blockIdx.y * 128;

    extern __shared__ char smem[];
    uint32_t sb = smem_to_u32(smem);
    __shared__ int s_src[128];
    int tid = threadIdx.x, warp = tid >> 5, lane = tid & 31;
    int warp_m = warp & 1, warp_n = warp >> 1;

    if (GATHER && tid < 128) {
        int r = row0 + tid;
        s_src[tid] = g_src[e * CAP + (r < cnt ? r : cnt - 1)];
    }
    __syncthreads();

    // cp.async assignments: 4 (row,chunk) pairs per thread for A and B
    const float* aptr[4]; const float* bptr[4];
    uint32_t adst[4], bdst[4];
#pragma unroll
    for (int it = 0; it < 4; it++) {
        int idx = it * 256 + tid;
        int row = idx >> 3, chunk = idx & 7;
        if (GATHER) {
            aptr[it] = Ag + (size_t)s_src[row] * KDIM + chunk * 4;
        } else {
            int rr = row0 + row; if (rr >= cnt) rr = cnt - 1;
            aptr[it] = Ag + ((size_t)e * CAP + rr) * KDIM + chunk * 4;
        }
        bptr[it] = Bg + ((size_t)e * NTOT + j0 + row) * KDIM + chunk * 4;
        uint32_t sw = (uint32_t)((chunk ^ (row & 7)) << 4);
        adst[it] = sb + row * 128 + sw;
        bdst[it] = sb + 16384 + row * 128 + sw;
    }

    // ldmatrix per-thread bases
    int qa = lane >> 3;
    int rowa = warp_m * 64 + (qa & 1) * 8 + (lane & 7);
    int cqa = qa >> 1;
    int rowb = warp_n * 32 + (lane & 7);
    int cqb = (lane >> 3) & 1;

    float acc[4][4][4];
#pragma unroll
    for (int mi = 0; mi < 4; mi++)
#pragma unroll
        for (int ni = 0; ni < 4; ni++)
#pragma unroll
            for (int q = 0; q < 4; q++) acc[mi][ni][q] = 0.f;

    auto issue = [&](int c, int s) {
        uint32_t off = (uint32_t)s * 32768;
#pragma unroll
        for (int it = 0; it < 4; it++) cp16(adst[it] + off, aptr[it] + c * 32);
#pragma unroll
        for (int it = 0; it < 4; it++) cp16(bdst[it] + off, bptr[it] + c * 32);
        CP_COMMIT();
    };

    // prologue: stages 0..2
    issue(0, 0); issue(1, 1); issue(2, 2);

    for (int c = 0; c < NK; c++) {
        int s = c & 3;
        int rem = NK - 1 - c;
        if (rem >= 2)      asm volatile("cp.async.wait_group 2;" ::: "memory");
        else if (rem == 1) asm volatile("cp.async.wait_group 1;" ::: "memory");
        else               asm volatile("cp.async.wait_group 0;" ::: "memory");
        __syncthreads();
        if (c + 3 < NK) issue(c + 3, (c + 3) & 3);

        uint32_t as = sb + (uint32_t)s * 32768;
        uint32_t bs = as + 16384;
#pragma unroll
        for (int ks = 0; ks < 4; ks++) {
            uint32_t a[4][4], b[4][2];
#pragma unroll
            for (int mi = 0; mi < 4; mi++)
                ldsm4(a[mi], as + (rowa + mi * 16) * 128
                              + (((ks * 2 + cqa) ^ (rowa & 7)) << 4));
#pragma unroll
            for (int ni = 0; ni < 4; ni++)
                ldsm2(b[ni], bs + (rowb + ni * 8) * 128
                              + (((ks * 2 + cqb) ^ (rowb & 7)) << 4));
#pragma unroll
            for (int mi = 0; mi < 4; mi++)
#pragma unroll
                for (int ni = 0; ni < 4; ni++)
                    mma_tf32(acc[mi][ni], a[mi], b[ni]);
        }
        __syncthreads();
    }

    // epilogue
#pragma unroll
    for (int mi = 0; mi < 4; mi++) {
        int r0t = row0 + warp_m * 64 + mi * 16 + (lane >> 2);
#pragma unroll
        for (int ni = 0; ni < 4; ni++) {
            int col = j0 + warp_n * 32 + ni * 8 + 2 * (lane & 3);
            float bb0 = __ldg(biasG + (size_t)e * NTOT + col);
            float bb1 = __ldg(biasG + (size_t)e * NTOT + col + 1);
            float v0 = acc[mi][ni][0] + bb0, v1 = acc[mi][ni][1] + bb1;
            float v2 = acc[mi][ni][2] + bb0, v3 = acc[mi][ni][3] + bb1;
            if (RELU) {
                v0 = rna_tf32(fmaxf(v0, 0.f)); v1 = rna_tf32(fmaxf(v1, 0.f));
                v2 = rna_tf32(fmaxf(v2, 0.f)); v3 = rna_tf32(fmaxf(v3, 0.f));
            }
            if (r0t < cnt) {
                float2 o = {v0, v1};
                *(float2*)(Cg + ((size_t)e * CAP + r0t) * NTOT + col) = o;
            }
            if (r0t + 8 < cnt) {
                float2 o = {v2, v3};
                *(float2*)(Cg + ((size_t)e * CAP + r0t + 8) * NTOT + col) = o;
            }
        }
    }
}

// ---------------- 6) combine -------------------------------------------------
__global__ __launch_bounds__(256) void k_combine(float* __restrict__ y) {
    int tid = threadIdx.x;
    int s = blockIdx.x * 4 + (tid >> 6);
    int m = (tid & 63) << 2;
    int sl0 = g_tokslot[s * 2 + 0], sl1 = g_tokslot[s * 2 + 1];
    float v0 = g_topv[s * 2 + 0],  v1 = g_topv[s * 2 + 1];
    float rx = 0.f, ry = 0.f, rz = 0.f, rw = 0.f;
    if (sl0 >= 0) {
        float4 a = *(const float4*)&g_eo[(size_t)sl0 * MDIM + m];
        rx += v0 * a.x; ry += v0 * a.y; rz += v0 * a.z; rw += v0 * a.w;
    }
    if (sl1 >= 0) {
        float4 a = *(const float4*)&g_eo[(size_t)sl1 * MDIM + m];
        rx += v1 * a.x; ry += v1 * a.y; rz += v1 * a.z; rw += v1 * a.w;
    }
    float4 o = {rx, ry, rz, rw};
    *(float4*)&y[(size_t)s * MDIM + m] = o;
}

// ---------------- launch -----------------------------------------------------
extern "C" void kernel_launch(void* const* d_in, const int* in_sizes, int n_in,
                              void* d_out, int out_size) {
    const float* x  = (const float*)d_in[0];
    const float* wg = (const float*)d_in[1];
    const float* w1 = (const float*)d_in[2];
    const float* b1 = (const float*)d_in[3];
    const float* w2 = (const float*)d_in[4];
    const float* b2 = (const float*)d_in[5];
    float* y = (float*)d_out;
    float* lossPtr = (out_size > SNUM * MDIM) ? (y + (size_t)SNUM * MDIM) : nullptr;

    float *xr, *w1t, *w2t, *hbuf, *eobuf;
    cudaGetSymbolAddress((void**)&xr,   g_xr);
    cudaGetSymbolAddress((void**)&w1t,  g_w1t);
    cudaGetSymbolAddress((void**)&w2t,  g_w2t);
    cudaGetSymbolAddress((void**)&hbuf, g_h);
    cudaGetSymbolAddress((void**)&eobuf, g_eo);

    cudaFuncSetAttribute(k_mma<8, HDIM, true, true>,
                         cudaFuncAttributeMaxDynamicSharedMemorySize, SMEM_BYTES);
    cudaFuncSetAttribute(k_mma<32, MDIM, false, false>,
                         cudaFuncAttributeMaxDynamicSharedMemorySize, SMEM_BYTES);

    k_xround<<<SNUM * MDIM / 1024, 256>>>(x, xr);
    k_transpose<<<dim3(HDIM / 32, MDIM / 32, ENUM), dim3(32, 8)>>>(w1, w1t, MDIM, HDIM);
    k_transpose<<<dim3(MDIM / 32, HDIM / 32, ENUM), dim3(32, 8)>>>(w2, w2t, HDIM, MDIM);
    k_gate <<<NB, 256>>>(x, wg);
    k_scan <<<1, 512>>>(lossPtr);
    k_route<<<NB, 256>>>();
    k_mma<8, HDIM, true, true>
        <<<dim3(CAP / 128, HDIM / 128, ENUM), 256, SMEM_BYTES>>>(xr, w1t, b1, hbuf);
    k_mma<32, MDIM, false, false>
        <<<dim3(CAP / 128, MDIM / 128, ENUM), 256, SMEM_BYTES>>>(hbuf, w2t, b2, eobuf);
    k_combine<<<SNUM / 4, 256>>>(y);
}

// round 5
// speedup vs baseline: 5.8853x; 1.6984x over previous
#include <cuda_runtime.h>
#include <cuda_fp16.h>
#include <cstdint>

#define SNUM 65536
#define MDIM 256
#define ENUM 8
#define HDIM 1024
#define CAP  20480          // TOP_K * int(1.25 * S/E)
#define NB   8192           // gating blocks, 8 tokens each

// ---------------- scratch (device globals; no allocations allowed) ----------
__device__ int   g_topi[SNUM * 2];
__device__ float g_topv[SNUM * 2];
__device__ int   g_blockcnt[NB * 16];
__device__ int   g_blockoff[NB * 16];
__device__ float g_blockgate[NB * ENUM];
__device__ int   g_k1base[ENUM];
__device__ int   g_cnt[ENUM];
__device__ int   g_src[ENUM * CAP];
__device__ int   g_tokslot[SNUM * 2];
__device__ __half g_xh [(size_t)SNUM * MDIM];          // fp16 x
__device__ __half g_w1t[(size_t)ENUM * HDIM * MDIM];   // [E][1024][256] fp16
__device__ __half g_w2t[(size_t)ENUM * MDIM * HDIM];   // [E][256][1024] fp16
__device__ __half g_h [(size_t)ENUM * CAP * HDIM];     // hidden fp16
__device__ float  g_eo[(size_t)ENUM * CAP * MDIM];     // expert outputs fp32

// ---------------- helpers ----------------------------------------------------
__device__ __forceinline__ uint32_t smem_to_u32(const void* p) {
    uint32_t a;
    asm("{ .reg .u64 t; cvta.to.shared.u64 t, %1; cvt.u32.u64 %0, t; }" : "=r"(a) : "l"(p));
    return a;
}
__device__ __forceinline__ void cp16(uint32_t dst, const void* src) {
    asm volatile("cp.async.cg.shared.global [%0], [%1], 16;" :: "r"(dst), "l"(src) : "memory");
}
#define CP_COMMIT() asm volatile("cp.async.commit_group;" ::: "memory")

__device__ __forceinline__ void ldsm4(uint32_t* r, uint32_t addr) {
    asm volatile("ldmatrix.sync.aligned.m8n8.x4.shared.b16 {%0,%1,%2,%3}, [%4];"
                 : "=r"(r[0]), "=r"(r[1]), "=r"(r[2]), "=r"(r[3]) : "r"(addr));
}
__device__ __forceinline__ void ldsm2(uint32_t* r, uint32_t addr) {
    asm volatile("ldmatrix.sync.aligned.m8n8.x2.shared.b16 {%0,%1}, [%2];"
                 : "=r"(r[0]), "=r"(r[1]) : "r"(addr));
}
__device__ __forceinline__ void mma_f16(float* c, const uint32_t* a, const uint32_t* b) {
    asm volatile("mma.sync.aligned.m16n8k16.row.col.f32.f16.f16.f32 "
                 "{%0,%1,%2,%3}, {%4,%5,%6,%7}, {%8,%9}, {%0,%1,%2,%3};"
                 : "+f"(c[0]), "+f"(c[1]), "+f"(c[2]), "+f"(c[3])
                 : "r"(a[0]), "r"(a[1]), "r"(a[2]), "r"(a[3]), "r"(b[0]), "r"(b[1]));
}

// ---------------- 0a) convert x to fp16 --------------------------------------
__global__ __launch_bounds__(256) void k_xhalf(const float* __restrict__ x,
                                               __half* __restrict__ xh) {
    size_t i = ((size_t)blockIdx.x * 256 + threadIdx.x) * 8;
    float4 v0 = *(const float4*)(x + i);
    float4 v1 = *(const float4*)(x + i + 4);
    __half2 o[4];
    o[0] = __floats2half2_rn(v0.x, v0.y);
    o[1] = __floats2half2_rn(v0.z, v0.w);
    o[2] = __floats2half2_rn(v1.x, v1.y);
    o[3] = __floats2half2_rn(v1.z, v1.w);
    *(uint4*)(xh + i) = *(const uint4*)o;
}

// ---------------- 0b) transpose + fp16 weights -------------------------------
// out[e][c][r] = half(in[e][r][c]);  grid (C/32, R/32, E), block (32,8)
__global__ void k_transpose(const float* __restrict__ in, __half* __restrict__ out,
                            int R, int C) {
    __shared__ float t[32][33];
    int e = blockIdx.z;
    const float* ine = in + (size_t)e * R * C;
    __half* oute = out + (size_t)e * R * C;
    int c0 = blockIdx.x * 32, r0 = blockIdx.y * 32;
    int tx = threadIdx.x, ty = threadIdx.y;
#pragma unroll
    for (int i = 0; i < 4; i++)
        t[ty + i * 8][tx] = ine[(size_t)(r0 + ty + i * 8) * C + c0 + tx];
    __syncthreads();
#pragma unroll
    for (int i = 0; i < 4; i++)
        oute[(size_t)(c0 + ty + i * 8) * R + r0 + tx] = __float2half_rn(t[tx][ty + i * 8]);
}

// ---------------- 1) gating --------------------------------------------------
__global__ __launch_bounds__(256) void k_gate(const float* __restrict__ x,
                                              const float* __restrict__ wg) {
    __shared__ float wgs[ENUM * MDIM];
    __shared__ int   scnt[16];
    __shared__ float sg[8][ENUM];
    int tid = threadIdx.x;
    for (int i = tid; i < ENUM * MDIM; i += 256) wgs[i] = wg[i];
    if (tid < 16) scnt[tid] = 0;
    __syncthreads();

    int warp = tid >> 5, lane = tid & 31;
    int s = blockIdx.x * 8 + warp;
    const float* xr = x + (size_t)s * MDIM;

    float part[ENUM];
#pragma unroll
    for (int e = 0; e < ENUM; e++) part[e] = 0.f;
#pragma unroll
    for (int i = 0; i < 8; i++) {
        float v = xr[i * 32 + lane];
#pragma unroll
        for (int e = 0; e < ENUM; e++) part[e] += v * wgs[e * MDIM + i * 32 + lane];
    }
#pragma unroll
    for (int e = 0; e < ENUM; e++) {
#pragma unroll
        for (int off = 16; off; off >>= 1)
            part[e] += __shfl_xor_sync(0xffffffffu, part[e], off);
    }

    if (lane == 0) {
        float mx = part[0];
#pragma unroll
        for (int e = 1; e < ENUM; e++) mx = fmaxf(mx, part[e]);
        float p[ENUM]; float sum = 0.f;
#pragma unroll
        for (int e = 0; e < ENUM; e++) { p[e] = expf(part[e] - mx); sum += p[e]; }
        float inv = 1.f / sum;
#pragma unroll
        for (int e = 0; e < ENUM; e++) { p[e] *= inv; sg[warp][e] = p[e]; }
        int i0 = 0; float v0 = p[0];
#pragma unroll
        for (int e = 1; e < ENUM; e++) if (p[e] > v0) { v0 = p[e]; i0 = e; }
        int i1 = -1; float v1 = -1.f;
#pragma unroll
        for (int e = 0; e < ENUM; e++) if (e != i0 && p[e] > v1) { v1 = p[e]; i1 = e; }
        g_topi[s * 2 + 0] = i0;  g_topi[s * 2 + 1] = i1;
        g_topv[s * 2 + 0] = v0;  g_topv[s * 2 + 1] = v1;
        atomicAdd(&scnt[i0 * 2 + 0], 1);
        atomicAdd(&scnt[i1 * 2 + 1], 1);
    }
    __syncthreads();
    if (tid < 16) g_blockcnt[blockIdx.x * 16 + tid] = scnt[tid];
    if (tid < ENUM) {
        float a = 0.f;
#pragma unroll
        for (int w = 0; w < 8; w++) a += sg[w][tid];
        g_blockgate[blockIdx.x * ENUM + tid] = a;
    }
}

// ---------------- 2) scan + loss ---------------------------------------------
__global__ __launch_bounds__(512) void k_scan(float* lossPtr) {
    int tid = threadIdx.x, w = tid >> 5, lane = tid & 31;
    __shared__ int   s_tot[16];
    __shared__ float s_gs[ENUM];
    int carry = 0;
    for (int c = 0; c < NB / 32; c++) {
        int idx = c * 32 + lane;
        int v = g_blockcnt[idx * 16 + w];
        int inc = v;
#pragma unroll
        for (int off = 1; off < 32; off <<= 1) {
            int t = __shfl_up_sync(0xffffffffu, inc, off);
            if (lane >= off) inc += t;
        }
        g_blockoff[idx * 16 + w] = carry + inc - v;
        carry += __shfl_sync(0xffffffffu, inc, 31);
    }
    if (lane == 0) s_tot[w] = carry;
    if (w < ENUM) {
        float acc = 0.f;
        for (int c = 0; c < NB / 32; c++)
            acc += g_blockgate[(c * 32 + lane) * ENUM + w];
#pragma unroll
        for (int off = 16; off; off >>= 1)
            acc += __shfl_xor_sync(0xffffffffu, acc, off);
        if (lane == 0) s_gs[w] = acc;
    }
    __syncthreads();
    if (tid == 0) {
        float loss = 0.f;
        for (int e = 0; e < ENUM; e++) {
            float me = s_gs[e] / (float)SNUM;
            float ce = (float)s_tot[e * 2] / (float)SNUM;
            loss += me * ce;
        }
        loss *= (float)ENUM;
        if (lossPtr) *lossPtr = loss;
        for (int e = 0; e < ENUM; e++) {
            g_k1base[e] = s_tot[e * 2];
            int t = s_tot[e * 2] + s_tot[e * 2 + 1];
            g_cnt[e] = t < CAP ? t : CAP;
        }
    }
}

// ---------------- 3) routing -------------------------------------------------
__global__ __launch_bounds__(256) void k_route() {
    __shared__ int ch[8][2];
    int tid = threadIdx.x, warp = tid >> 5, lane = tid & 31;
    int s = blockIdx.x * 8 + warp;
    if (lane < 2) ch[warp][lane] = g_topi[s * 2 + lane];
    __syncthreads();
    if (tid < 16) {
        int t = tid >> 1, k = tid & 1;
        int s2 = blockIdx.x * 8 + t;
        int e = ch[t][k];
        int rank = 0;
#pragma unroll
        for (int u = 0; u < 8; u++) rank += (u < t) && (ch[u][k] == e);
        int pos = g_blockoff[blockIdx.x * 16 + e * 2 + k] + rank
                + (k ? g_k1base[e] : 0);
        int slot = -1;
        if (pos < CAP) { slot = e * CAP + pos; g_src[slot] = s2; }
        g_tokslot[s2 * 2 + k] = slot;
    }
}

// ---------------- 4/5) fp16 mma.sync GEMM, tile 128x128x64, 3-stage ---------
// smem per stage: A 128x64 fp16 (16KB, 128B rows, XOR-8 swizzle) + B same
#define STAGES 3
#define SMEM_BYTES (STAGES * 32768)

template<int NK, int NTOT, bool GATHER, bool RELU, typename CT>
__global__ __launch_bounds__(256) void k_mma(
    const __half* __restrict__ Ag, const __half* __restrict__ Bg,
    const float* __restrict__ biasG, CT* __restrict__ Cg)
{
    constexpr int KDIM = NK * 64;
    int e = blockIdx.z;
    int cnt = g_cnt[e];
    int row0 = blockIdx.x * 128;
    if (row0 >= cnt) return;
    int j0 = blockIdx.y * 128;

    extern __shared__ char smem[];
    uint32_t sb = smem_to_u32(smem);
    __shared__ int s_src[128];
    int tid = threadIdx.x, warp = tid >> 5, lane = tid & 31;
    int warp_m = warp & 1, warp_n = warp >> 1;

    if (GATHER && tid < 128) {
        int r = row0 + tid;
        s_src[tid] = g_src[e * CAP + (r < cnt ? r : cnt - 1)];
    }
    __syncthreads();

    // cp.async: 4 (row,chunk16B) pairs per thread for A and B (128 rows x 8 units)
    const __half* aptr[4]; const __half* bptr[4];
    uint32_t adst[4], bdst[4];
#pragma unroll
    for (int it = 0; it < 4; it++) {
        int idx = it * 256 + tid;
        int row = idx >> 3, chunk = idx & 7;
        if (GATHER) {
            aptr[it] = Ag + (size_t)s_src[row] * KDIM + chunk * 8;
        } else {
            int rr = row0 + row; if (rr >= cnt) rr = cnt - 1;
            aptr[it] = Ag + ((size_t)e * CAP + rr) * KDIM + chunk * 8;
        }
        bptr[it] = Bg + ((size_t)e * NTOT + j0 + row) * KDIM + chunk * 8;
        uint32_t sw = (uint32_t)((chunk ^ (row & 7)) << 4);
        adst[it] = sb + row * 128 + sw;
        bdst[it] = sb + 16384 + row * 128 + sw;
    }

    // ldmatrix per-thread bases
    int rowa_b = warp_m * 64 + (lane & 7) + ((lane >> 3) & 1) * 8;  // + mi*16
    int kua = lane >> 4;                                            // 0/1 (16B unit)
    int rowb_b = warp_n * 32 + (lane & 7);                          // + ni*8
    int kub = (lane >> 3) & 1;

    float acc[4][4][4];
#pragma unroll
    for (int mi = 0; mi < 4; mi++)
#pragma unroll
        for (int ni = 0; ni < 4; ni++)
#pragma unroll
            for (int q = 0; q < 4; q++) acc[mi][ni][q] = 0.f;

    auto issue = [&](int c, int s) {
        uint32_t off = (uint32_t)s * 32768;
#pragma unroll
        for (int it = 0; it < 4; it++) cp16(adst[it] + off, aptr[it] + c * 64);
#pragma unroll
        for (int it = 0; it < 4; it++) cp16(bdst[it] + off, bptr[it] + c * 64);
        CP_COMMIT();
    };

    // prologue: stages 0..2
    issue(0, 0);
    if (NK > 1) issue(1, 1);
    if (NK > 2) issue(2, 2);

    int stage = 0;
    for (int c = 0; c < NK; c++) {
        int rem = NK - 1 - c;
        if (rem >= 2)      asm volatile("cp.async.wait_group 2;" ::: "memory");
        else if (rem == 1) asm volatile("cp.async.wait_group 1;" ::: "memory");
        else               asm volatile("cp.async.wait_group 0;" ::: "memory");
        __syncthreads();

        uint32_t as = sb + (uint32_t)stage * 32768;
        uint32_t bs = as + 16384;
#pragma unroll
        for (int ks = 0; ks < 4; ks++) {
            uint32_t a[4][4], b[4][2];
#pragma unroll
            for (int mi = 0; mi < 4; mi++) {
                int row = rowa_b + mi * 16;
                ldsm4(a[mi], as + row * 128 + (((ks * 2 + kua) ^ (row & 7)) << 4));
            }
#pragma unroll
            for (int ni = 0; ni < 4; ni++) {
                int row = rowb_b + ni * 8;
                ldsm2(b[ni], bs + row * 128 + (((ks * 2 + kub) ^ (row & 7)) << 4));
            }
#pragma unroll
            for (int mi = 0; mi < 4; mi++)
#pragma unroll
                for (int ni = 0; ni < 4; ni++)
                    mma_f16(acc[mi][ni], a[mi], b[ni]);
        }
        __syncthreads();
        if (c + STAGES < NK) issue(c + STAGES, stage);
        stage = (stage == STAGES - 1) ? 0 : stage + 1;
    }

    // epilogue
#pragma unroll
    for (int mi = 0; mi < 4; mi++) {
        int r0t = row0 + warp_m * 64 + mi * 16 + (lane >> 2);
#pragma unroll
        for (int ni = 0; ni < 4; ni++) {
            int col = j0 + warp_n * 32 + ni * 8 + 2 * (lane & 3);
            float bb0 = __ldg(biasG + (size_t)e * NTOT + col);
            float bb1 = __ldg(biasG + (size_t)e * NTOT + col + 1);
            float v0 = acc[mi][ni][0] + bb0, v1 = acc[mi][ni][1] + bb1;
            float v2 = acc[mi][ni][2] + bb0, v3 = acc[mi][ni][3] + bb1;
            if (RELU) {
                v0 = fmaxf(v0, 0.f); v1 = fmaxf(v1, 0.f);
                v2 = fmaxf(v2, 0.f); v3 = fmaxf(v3, 0.f);
            }
            if (sizeof(CT) == 2) {
                __half2* base = (__half2*)Cg;
                if (r0t < cnt)
                    base[(((size_t)e * CAP + r0t) * NTOT + col) >> 1] = __floats2half2_rn(v0, v1);
                if (r0t + 8 < cnt)
                    base[(((size_t)e * CAP + r0t + 8) * NTOT + col) >> 1] = __floats2half2_rn(v2, v3);
            } else {
                float* base = (float*)Cg;
                if (r0t < cnt) {
                    float2 o = {v0, v1};
                    *(float2*)(base + ((size_t)e * CAP + r0t) * NTOT + col) = o;
                }
                if (r0t + 8 < cnt) {
                    float2 o = {v2, v3};
                    *(float2*)(base + ((size_t)e * CAP + r0t + 8) * NTOT + col) = o;
                }
            }
        }
    }
}

// ---------------- 6) combine -------------------------------------------------
__global__ __launch_bounds__(256) void k_combine(float* __restrict__ y) {
    int tid = threadIdx.x;
    int s = blockIdx.x * 4 + (tid >> 6);
    int m = (tid & 63) << 2;
    int sl0 = g_tokslot[s * 2 + 0], sl1 = g_tokslot[s * 2 + 1];
    float v0 = g_topv[s * 2 + 0],  v1 = g_topv[s * 2 + 1];
    float rx = 0.f, ry = 0.f, rz = 0.f, rw = 0.f;
    if (sl0 >= 0) {
        float4 a = *(const float4*)&g_eo[(size_t)sl0 * MDIM + m];
        rx += v0 * a.x; ry += v0 * a.y; rz += v0 * a.z; rw += v0 * a.w;
    }
    if (sl1 >= 0) {
        float4 a = *(const float4*)&g_eo[(size_t)sl1 * MDIM + m];
        rx += v1 * a.x; ry += v1 * a.y; rz += v1 * a.z; rw += v1 * a.w;
    }
    float4 o = {rx, ry, rz, rw};
    *(float4*)&y[(size_t)s * MDIM + m] = o;
}

// ---------------- launch -----------------------------------------------------
extern "C" void kernel_launch(void* const* d_in, const int* in_sizes, int n_in,
                              void* d_out, int out_size) {
    const float* x  = (const float*)d_in[0];
    const float* wg = (const float*)d_in[1];
    const float* w1 = (const float*)d_in[2];
    const float* b1 = (const float*)d_in[3];
    const float* w2 = (const float*)d_in[4];
    const float* b2 = (const float*)d_in[5];
    float* y = (float*)d_out;
    float* lossPtr = (out_size > SNUM * MDIM) ? (y + (size_t)SNUM * MDIM) : nullptr;

    __half *xh, *w1t, *w2t, *hbuf;
    float *eobuf;
    cudaGetSymbolAddress((void**)&xh,   g_xh);
    cudaGetSymbolAddress((void**)&w1t,  g_w1t);
    cudaGetSymbolAddress((void**)&w2t,  g_w2t);
    cudaGetSymbolAddress((void**)&hbuf, g_h);
    cudaGetSymbolAddress((void**)&eobuf, g_eo);

    cudaFuncSetAttribute(k_mma<4, HDIM, true, true, __half>,
                         cudaFuncAttributeMaxDynamicSharedMemorySize, SMEM_BYTES);
    cudaFuncSetAttribute(k_mma<16, MDIM, false, false, float>,
                         cudaFuncAttributeMaxDynamicSharedMemorySize, SMEM_BYTES);

    k_xhalf<<<SNUM * MDIM / 2048, 256>>>(x, xh);
    k_transpose<<<dim3(HDIM / 32, MDIM / 32, ENUM), dim3(32, 8)>>>(w1, w1t, MDIM, HDIM);
    k_transpose<<<dim3(MDIM / 32, HDIM / 32, ENUM), dim3(32, 8)>>>(w2, w2t, HDIM, MDIM);
    k_gate <<<NB, 256>>>(x, wg);
    k_scan <<<1, 512>>>(lossPtr);
    k_route<<<NB, 256>>>();
    k_mma<4, HDIM, true, true, __half>
        <<<dim3(CAP / 128, HDIM / 128, ENUM), 256, SMEM_BYTES>>>(xh, w1t, b1, hbuf);
    k_mma<16, MDIM, false, false, float>
        <<<dim3(CAP / 128, MDIM / 128, ENUM), 256, SMEM_BYTES>>>(hbuf, w2t, b2, eobuf);
    k_combine<<<SNUM / 4, 256>>>(y);
}